// round 7
// baseline (speedup 1.0000x reference)
#include <cuda_runtime.h>
#include <cstdint>

// snn_input: integrate-and-fire over T=32 steps, N=4194304 neurons.
//   per step: m += image[t]; spk = m >= 1.0f; m -= 1.0f if spk
// Output: [spikes (T*N, 0/1 float32), final mempot (N float32)].
// HBM-bound (1.056 GB irreducible traffic), ~84% of spec achieved so far.
// R7: 256-bit global accesses (sm_100+ ld/st.global.v8.f32). One warp
// instruction covers 1024B dense per stream (vs 512B with float4),
// fully-covered 128B lines (unlike R3's strided pair), halved LSU requests.

static constexpr int TSTEPS = 32;
static constexpr int TBATCH = 8;
static constexpr float THRES = 1.0f;

struct alignas(32) f8 { float v[8]; };

__device__ __forceinline__ f8 ldg256_cs(const float* p) {
    f8 r;
    asm volatile(
        "ld.global.cs.v8.f32 {%0,%1,%2,%3,%4,%5,%6,%7}, [%8];"
        : "=f"(r.v[0]), "=f"(r.v[1]), "=f"(r.v[2]), "=f"(r.v[3]),
          "=f"(r.v[4]), "=f"(r.v[5]), "=f"(r.v[6]), "=f"(r.v[7])
        : "l"(p));
    return r;
}

__device__ __forceinline__ void stg256_cs(float* p, const f8& r) {
    asm volatile(
        "st.global.cs.v8.f32 [%0], {%1,%2,%3,%4,%5,%6,%7,%8};"
        :: "l"(p),
           "f"(r.v[0]), "f"(r.v[1]), "f"(r.v[2]), "f"(r.v[3]),
           "f"(r.v[4]), "f"(r.v[5]), "f"(r.v[6]), "f"(r.v[7])
        : "memory");
}

__global__ __launch_bounds__(256) void snn_if_kernel(
    const float* __restrict__ image,    // [T, N]
    const float* __restrict__ mempot0,  // [N]
    float* __restrict__ out,            // [T*N spikes][N mempot]
    int n)
{
    // thread owns 8 consecutive floats, loaded/stored as ONE 256-bit access
    size_t i = ((size_t)blockIdx.x * blockDim.x + threadIdx.x) * 8;
    if (i >= (size_t)n) return;

    f8 m = ldg256_cs(&mempot0[i]);

#pragma unroll
    for (int tb = 0; tb < TSTEPS / TBATCH; tb++) {
        f8 im[TBATCH];
        // front-batched loads: TBATCH independent LDG.E.256 in flight
#pragma unroll
        for (int j = 0; j < TBATCH; j++) {
            im[j] = ldg256_cs(&image[(size_t)(tb * TBATCH + j) * n + i]);
        }
        // compute + store burst
#pragma unroll
        for (int j = 0; j < TBATCH; j++) {
            f8 s;
#pragma unroll
            for (int k = 0; k < 8; k++) {
                float mv = m.v[k] + im[j].v[k];
                float sv = (mv >= THRES) ? 1.0f : 0.0f;
                m.v[k] = mv - sv;   // thres == 1.0 -> subtract spike directly
                s.v[k] = sv;
            }
            stg256_cs(&out[(size_t)(tb * TBATCH + j) * n + i], s);
        }
    }
    stg256_cs(&out[(size_t)TSTEPS * n + i], m);
}

extern "C" void kernel_launch(void* const* d_in, const int* in_sizes, int n_in,
                              void* d_out, int out_size)
{
    const float* image   = (const float*)d_in[0];
    const float* mempot0 = (const float*)d_in[1];
    float*       out     = (float*)d_out;

    int n = in_sizes[1];               // 4194304 neurons
    int nthreads_total = n / 8;        // 524288 threads

    const int threads = 256;
    const int blocks  = (nthreads_total + threads - 1) / threads;
    snn_if_kernel<<<blocks, threads>>>(image, mempot0, out, n);
}

// round 8
// speedup vs baseline: 1.0141x; 1.0141x over previous
#include <cuda_runtime.h>
#include <cstdint>

// snn_input: integrate-and-fire over T=32 steps, N=4194304 neurons.
//   per step: m += image[t]; spk = m >= 1.0f; m -= 1.0f if spk
// Output: [spikes (T*N, 0/1 float32), final mempot (N float32)].
//
// 1.056 GB irreducible traffic, all of it through L2. Measured plateau
// across float4/v8f32 x TBATCH{8,16} variants: 6.64-6.65 TB/s = the
// path-independent LTS throughput cap (~6300 B/cyc), which binds before
// HBM. This is the roofline; kernel is memory-path saturated.
//
// Config: fully-coalesced 1 float4/thread, 16 timesteps of loads
// front-batched (MLP=16), streaming .cs both directions, exact grid
// (no bounds predicate).

static constexpr int TSTEPS = 32;
static constexpr int TBATCH = 16;
static constexpr float THRES = 1.0f;

__global__ __launch_bounds__(256) void snn_if_kernel(
    const float4* __restrict__ image,    // [T, N/4] as float4
    const float4* __restrict__ mempot0,  // [N/4]
    float4* __restrict__ out,            // [T*N/4 spikes][N/4 mempot]
    int n4)
{
    int i = blockIdx.x * blockDim.x + threadIdx.x;   // grid covers n4 exactly

    float4 m = __ldcs(&mempot0[i]);

#pragma unroll
    for (int tb = 0; tb < TSTEPS / TBATCH; tb++) {
        float4 im[TBATCH];
        // front-batched loads: 16 independent LDG.E.128.CS in flight
#pragma unroll
        for (int j = 0; j < TBATCH; j++) {
            im[j] = __ldcs(&image[(size_t)(tb * TBATCH + j) * n4 + i]);
        }
        // compute + store burst
#pragma unroll
        for (int j = 0; j < TBATCH; j++) {
            m.x += im[j].x; m.y += im[j].y; m.z += im[j].z; m.w += im[j].w;
            float4 s;
            s.x = (m.x >= THRES) ? 1.0f : 0.0f;
            s.y = (m.y >= THRES) ? 1.0f : 0.0f;
            s.z = (m.z >= THRES) ? 1.0f : 0.0f;
            s.w = (m.w >= THRES) ? 1.0f : 0.0f;
            // thres == 1.0 so subtracting s == subtracting s*THRES
            m.x -= s.x; m.y -= s.y; m.z -= s.z; m.w -= s.w;
            __stcs(&out[(size_t)(tb * TBATCH + j) * n4 + i], s);
        }
    }
    __stcs(&out[(size_t)TSTEPS * n4 + i], m);
}

extern "C" void kernel_launch(void* const* d_in, const int* in_sizes, int n_in,
                              void* d_out, int out_size)
{
    const float4* image   = (const float4*)d_in[0];
    const float4* mempot0 = (const float4*)d_in[1];
    float4*       out     = (float4*)d_out;

    int n  = in_sizes[1];      // 4194304 neurons
    int n4 = n / 4;            // 1048576 float4 lanes (= 4096 * 256 exactly)

    const int threads = 256;
    const int blocks  = n4 / threads;
    snn_if_kernel<<<blocks, threads>>>(image, mempot0, out, n4);
}